// round 14
// baseline (speedup 1.0000x reference)
#include <cuda_runtime.h>
#include <cuda_fp16.h>
#include <cstdint>

// Problem constants
#define BB   2
#define TT   260
#define HH   4
#define DD   1024
#define VV   32000
#define DFF  2048
#define MM   512

// ---------------------------------------------------------------------------
// Persistent scratch (__device__ globals; no allocations allowed)
// ---------------------------------------------------------------------------
#define OFF_PROJ 0
#define OFF_SAWV 8388608
#define OFF_SAWO 12582912
#define OFF_CAWV 16777216
#define OFF_CAWO 20971520
#define OFF_FF1  25165824
#define OFF_FF2  33554432
#define OFF_UNE  41943040
#define W_TOTAL  74711040

__device__ __half g_wh[W_TOTAL];                 // single-fp16 weights

__device__ float g_x  [MM * DD];
__device__ float g_t2 [MM * DD];
__device__ __half g_xc_hi[MM * 2 * DD], g_xc_lo[MM * 2 * DD];
__device__ __half g_x_hi [HH][MM * DD], g_x_lo [HH][MM * DD];  // per-head
__device__ __half g_t1_hi[MM * DFF],    g_t1_lo[MM * DFF];

// ---------------------------------------------------------------------------
// helpers
// ---------------------------------------------------------------------------
__device__ __forceinline__ float block_sum(float v) {
    __shared__ float sh[32];
    const int lane = threadIdx.x & 31;
    const int wid  = threadIdx.x >> 5;
    #pragma unroll
    for (int o = 16; o; o >>= 1) v += __shfl_xor_sync(0xffffffffu, v, o);
    if (lane == 0) sh[wid] = v;
    __syncthreads();
    if (wid == 0) {
        v = (lane < 8) ? sh[lane] : 0.0f;
        #pragma unroll
        for (int o = 4; o; o >>= 1) v += __shfl_xor_sync(0xffffffffu, v, o);
        if (lane == 0) sh[0] = v;
    }
    __syncthreads();
    v = sh[0];
    __syncthreads();
    return v;
}

__device__ __forceinline__ uint32_t s2u(const void* p) {
    uint32_t a;
    asm("{ .reg .u64 t; cvta.to.shared.u64 t, %1; cvt.u32.u64 %0, t; }" : "=r"(a) : "l"(p));
    return a;
}
__device__ __forceinline__ void ldsm4(uint32_t* r, uint32_t addr) {
    asm volatile("ldmatrix.sync.aligned.m8n8.x4.shared.b16 {%0,%1,%2,%3}, [%4];"
                 : "=r"(r[0]), "=r"(r[1]), "=r"(r[2]), "=r"(r[3]) : "r"(addr));
}
__device__ __forceinline__ void mma_f16(float* c, const uint32_t* a, const uint32_t* b) {
    asm volatile(
        "mma.sync.aligned.m16n8k16.row.col.f32.f16.f16.f32 "
        "{%0,%1,%2,%3}, {%4,%5,%6,%7}, {%8,%9}, {%0,%1,%2,%3};"
        : "+f"(c[0]), "+f"(c[1]), "+f"(c[2]), "+f"(c[3])
        : "r"(a[0]), "r"(a[1]), "r"(a[2]), "r"(a[3]), "r"(b[0]), "r"(b[1]));
}
__device__ __forceinline__ void split_h(float f, __half& h, __half& l) {
    h = __float2half_rn(f);
    l = __float2half_rn(f - __half2float(h));
}
__device__ __forceinline__ uint32_t pack_h2(__half a, __half b) {
    __half2 p = __halves2half2(a, b);
    return *reinterpret_cast<uint32_t*>(&p);
}

// ---------------------------------------------------------------------------
// weight conversion: fp32 -> single fp16
// ---------------------------------------------------------------------------
__global__ void conv_w(const float* __restrict__ src, __half* __restrict__ dst, int n4) {
    int i = blockIdx.x * blockDim.x + threadIdx.x;
    const int stride = gridDim.x * blockDim.x;
    for (; i < n4; i += stride) {
        float4 v = ((const float4*)src)[i];
        uint32_t p0 = pack_h2(__float2half_rn(v.x), __float2half_rn(v.y));
        uint32_t p1 = pack_h2(__float2half_rn(v.z), __float2half_rn(v.w));
        ((uint2*)dst)[i] = make_uint2(p0, p1);
    }
}

__global__ void init_h_kernel(const float* __restrict__ hidden, float* __restrict__ hbuf) {
    const int m = blockIdx.x;
    const int b = m >> 8, j = m & 255;
    const float* src = hidden + ((size_t)b * TT + j) * DD;
    float* dst = hbuf + (size_t)m * DD;
    #pragma unroll
    for (int i = 0; i < 4; i++) dst[threadIdx.x + i * 256] = src[threadIdx.x + i * 256];
}

__global__ void prep_kernel(const int* __restrict__ tok,
                            const float* __restrict__ emb,
                            const float* __restrict__ hprev,
                            const float* __restrict__ rms_w,
                            __half* __restrict__ xch,
                            __half* __restrict__ xcl, int h) {
    const int m = blockIdx.x;
    const int half = blockIdx.y;
    const int tid = threadIdx.x;
    const int b = m >> 8, j = m & 255;
    const float* src;
    if (half == 0) {
        const int t = tok[b * TT + 1 + h + j];
        src = emb + (size_t)t * DD;
    } else {
        src = hprev + (size_t)m * DD;
    }
    float v[4];
    float ss = 0.0f;
    #pragma unroll
    for (int i = 0; i < 4; i++) { v[i] = src[tid + i * 256]; ss += v[i] * v[i]; }
    ss = block_sum(ss);
    const float s = rsqrtf(ss * (1.0f / DD) + 1e-6f);
    const size_t base = (size_t)m * (2 * DD) + half * DD;
    #pragma unroll
    for (int i = 0; i < 4; i++) {
        const int d = tid + i * 256;
        const float f = v[i] * s * rms_w[d];
        __half hh, ll;
        split_h(f, hh, ll);
        xch[base + d] = hh;
        xcl[base + d] = ll;
    }
}

__global__ void resid_ln_kernel(float* __restrict__ x, const float* __restrict__ u,
                                const float* __restrict__ w, const float* __restrict__ bb,
                                __half* __restrict__ oh, __half* __restrict__ ol) {
    const int m = blockIdx.x;
    const int tid = threadIdx.x;
    float* xr = x + (size_t)m * DD;
    const float* ur = u + (size_t)m * DD;
    float v[4];
    float s = 0.0f;
    #pragma unroll
    for (int i = 0; i < 4; i++) {
        v[i] = xr[tid + i * 256] + ur[tid + i * 256];
        s += v[i];
    }
    s = block_sum(s);
    const float mu = s * (1.0f / DD);
    float s2 = 0.0f;
    #pragma unroll
    for (int i = 0; i < 4; i++) { const float d = v[i] - mu; s2 += d * d; }
    s2 = block_sum(s2);
    const float rs = rsqrtf(s2 * (1.0f / DD) + 1e-5f);
    #pragma unroll
    for (int i = 0; i < 4; i++) {
        const int d = tid + i * 256;
        const float f = (v[i] - mu) * rs * w[d] + bb[d];
        xr[d] = f;
        __half hh, ll;
        split_h(f, hh, ll);
        oh[(size_t)m * DD + d] = hh;
        ol[(size_t)m * DD + d] = ll;
    }
}

// ---------------------------------------------------------------------------
// fp16 GEMM: C[m,n] = sum_k A[m,k]*B[n,k] + bias[n]
// NPROD=2: A = (Ahi + Alo) fp16 hi/lo pair   (chain)
// NPROD=1: A = Ahi only                      (unembed)
// ---------------------------------------------------------------------------
template<int BM, int BN, int WGM, int WGN, int NTH, int S, int NPROD>
__global__ void __launch_bounds__(NTH) gemm_fp16(
    const __half* __restrict__ Ahi, const __half* __restrict__ Alo,
    const __half* __restrict__ Bh,
    const float* __restrict__ bias,
    float* __restrict__ C, long long ldc,
    __half* __restrict__ Ohi, __half* __restrict__ Olo, int ldo,
    int K, int relu)
{
    constexpr int WM  = BM / WGM;
    constexpr int WN  = BN / WGN;
    constexpr int MI  = WM / 16;
    constexpr int NI  = WN / 8;
    constexpr int LS  = 40;
    constexpr int AT  = BM * LS * 2;
    constexpr int BT  = BN * LS * 2;
    constexpr int STAGE = NPROD * AT + BT;

    extern __shared__ char smem[];
    const uint32_t sb = s2u(smem);

    const int tid  = threadIdx.x;
    const int wid  = tid >> 5;
    const int lane = tid & 31;
    const int wm   = wid / WGN;
    const int wn   = wid % WGN;
    const int m0   = blockIdx.x * BM;
    const int n0   = blockIdx.y * BN;
    const int nCh  = K >> 5;

    float acc[MI][NI][4];
    #pragma unroll
    for (int i = 0; i < MI; i++)
        #pragma unroll
        for (int j = 0; j < NI; j++)
            #pragma unroll
            for (int q = 0; q < 4; q++) acc[i][j][q] = 0.0f;

    auto issue = [&](int c) {
        if (c < nCh) {
            const int k0 = c << 5;
            const uint32_t st = sb + (uint32_t)(c % S) * STAGE;
            #pragma unroll
            for (int q = tid; q < BM * 4; q += NTH) {
                const int row = q >> 2, col = (q & 3) << 3;
                const size_t off = (size_t)(m0 + row) * K + k0 + col;
                const uint32_t d = st + (uint32_t)(row * LS + col) * 2u;
                asm volatile("cp.async.cg.shared.global [%0], [%1], 16;" :: "r"(d), "l"(Ahi + off));
                if (NPROD == 2)
                    asm volatile("cp.async.cg.shared.global [%0], [%1], 16;" :: "r"(d + AT), "l"(Alo + off));
            }
            #pragma unroll
            for (int q = tid; q < BN * 4; q += NTH) {
                const int row = q >> 2, col = (q & 3) << 3;
                const size_t off = (size_t)(n0 + row) * K + k0 + col;
                const uint32_t d = st + NPROD * AT + (uint32_t)(row * LS + col) * 2u;
                asm volatile("cp.async.cg.shared.global [%0], [%1], 16;" :: "r"(d), "l"(Bh + off));
            }
        }
        asm volatile("cp.async.commit_group;" ::: "memory");
    };

    #pragma unroll
    for (int p = 0; p < S - 1; p++) issue(p);

    for (int c = 0; c < nCh; c++) {
        asm volatile("cp.async.wait_group %0;" :: "n"(S - 2) : "memory");
        __syncthreads();
        issue(c + S - 1);

        const uint32_t st  = sb + (uint32_t)(c % S) * STAGE;
        const uint32_t sAh = st;
        const uint32_t sBh = st + NPROD * AT;
        #pragma unroll
        for (int ks = 0; ks < 2; ks++) {
            uint32_t ah[MI][4], al[MI][4];
            #pragma unroll
            for (int mi = 0; mi < MI; mi++) {
                const int row = wm * WM + mi * 16 + (lane & 15);
                const int col = ks * 16 + (lane >> 4) * 8;
                const uint32_t ad = sAh + (uint32_t)(row * LS + col) * 2u;
                ldsm4(ah[mi], ad);
                if (NPROD == 2) ldsm4(al[mi], ad + AT);
            }
            uint32_t bh[NI][2];
            #pragma unroll
            for (int ni = 0; ni < NI; ni += 2) {
                const int g = lane >> 3;
                const int row = wn * WN + ni * 8 + ((g >> 1) << 3) + (lane & 7);
                const int col = ks * 16 + ((g & 1) << 3);
                const uint32_t bd = sBh + (uint32_t)(row * LS + col) * 2u;
                ldsm4(&bh[ni][0], bd);
            }
            #pragma unroll
            for (int mi = 0; mi < MI; mi++)
                #pragma unroll
                for (int ni = 0; ni < NI; ni++)
                    mma_f16(acc[mi][ni], ah[mi], bh[ni]);
            if (NPROD == 2) {
                #pragma unroll
                for (int mi = 0; mi < MI; mi++)
                    #pragma unroll
                    for (int ni = 0; ni < NI; ni++)
                        mma_f16(acc[mi][ni], al[mi], bh[ni]);
            }
        }
    }

    #pragma unroll
    for (int mi = 0; mi < MI; mi++) {
        #pragma unroll
        for (int ni = 0; ni < NI; ni++) {
            const int r0 = m0 + wm * WM + mi * 16 + (lane >> 2);
            const int cc = n0 + wn * WN + ni * 8 + ((lane & 3) << 1);
            const float b0 = bias[cc], b1 = bias[cc + 1];
            float v0 = acc[mi][ni][0] + b0;
            float v1 = acc[mi][ni][1] + b1;
            float v2 = acc[mi][ni][2] + b0;
            float v3 = acc[mi][ni][3] + b1;
            if (relu) {
                v0 = fmaxf(v0, 0.0f); v1 = fmaxf(v1, 0.0f);
                v2 = fmaxf(v2, 0.0f); v3 = fmaxf(v3, 0.0f);
            }
            if (C) {
                *(float2*)(C + (size_t)r0 * (size_t)ldc + cc)       = make_float2(v0, v1);
                *(float2*)(C + (size_t)(r0 + 8) * (size_t)ldc + cc) = make_float2(v2, v3);
            }
            if (Ohi) {
                __half h0, l0, h1, l1, h2, l2, h3, l3;
                split_h(v0, h0, l0); split_h(v1, h1, l1);
                split_h(v2, h2, l2); split_h(v3, h3, l3);
                *(uint32_t*)(Ohi + (size_t)r0 * ldo + cc)       = pack_h2(h0, h1);
                *(uint32_t*)(Olo + (size_t)r0 * ldo + cc)       = pack_h2(l0, l1);
                *(uint32_t*)(Ohi + (size_t)(r0 + 8) * ldo + cc) = pack_h2(h2, h3);
                *(uint32_t*)(Olo + (size_t)(r0 + 8) * ldo + cc) = pack_h2(l2, l3);
            }
        }
    }
}

// chain: 64x32 tile, 128 threads (WGM=2,WGN=2 -> warp tile 32x16, MI=2/NI=2),
// NPROD=2, 6 stages. stage = (2*64+32)*40*2 = 12800 B -> 76800 B (2 CTAs/SM).
#define SMEM_SMALL (6 * (2 * 64 * 40 * 2 + 32 * 40 * 2))
// unembed: 128x256, NPROD=1, 3 stages -> 3*(10240 + 20480) = 92160 B
#define SMEM_UNE   (3 * (128 * 40 * 2 + 256 * 40 * 2))

typedef void (*gemm_t)(const __half*, const __half*, const __half*,
                       const float*, float*, long long,
                       __half*, __half*, int, int, int);

// ---------------------------------------------------------------------------
// Host orchestration
// ---------------------------------------------------------------------------
extern "C" void kernel_launch(void* const* d_in, const int* in_sizes, int n_in,
                              void* d_out, int out_size) {
    const int*   tok     = (const int*)  d_in[0];
    const float* hidden  = (const float*)d_in[1];
    const float* emb     = (const float*)d_in[2];
    const float* rms_w   = (const float*)d_in[3];
    const float* proj_w  = (const float*)d_in[4];
    const float* proj_b  = (const float*)d_in[5];
    const float* sa_wv   = (const float*)d_in[6];
    const float* sa_bv   = (const float*)d_in[7];
    const float* sa_wo   = (const float*)d_in[8];
    const float* sa_bo   = (const float*)d_in[9];
    const float* ca_wv   = (const float*)d_in[10];
    const float* ca_bv   = (const float*)d_in[11];
    const float* ca_wo   = (const float*)d_in[12];
    const float* ca_bo   = (const float*)d_in[13];
    const float* ln1_w   = (const float*)d_in[14];
    const float* ln1_b   = (const float*)d_in[15];
    const float* ln2_w   = (const float*)d_in[16];
    const float* ln2_b   = (const float*)d_in[17];
    const float* ln3_w   = (const float*)d_in[18];
    const float* ln3_b   = (const float*)d_in[19];
    const float* ff_w1   = (const float*)d_in[20];
    const float* ff_b1   = (const float*)d_in[21];
    const float* ff_w2   = (const float*)d_in[22];
    const float* ff_b2   = (const float*)d_in[23];
    const float* unemb_w = (const float*)d_in[24];
    const float* unemb_b = (const float*)d_in[25];
    float* out = (float*)d_out;

    static __half *wh = nullptr;
    static __half *xch = nullptr, *xcl = nullptr;
    static __half *xhB = nullptr, *xlB = nullptr;
    static __half *t1h = nullptr, *t1l = nullptr;
    static float *x = nullptr, *t2 = nullptr;
    static cudaStream_t s2 = nullptr;
    static cudaEvent_t evStart = nullptr, evDone = nullptr, evH[HH] = {};
    if (!wh) {
        cudaGetSymbolAddress((void**)&wh,  g_wh);
        cudaGetSymbolAddress((void**)&xch, g_xc_hi);
        cudaGetSymbolAddress((void**)&xcl, g_xc_lo);
        cudaGetSymbolAddress((void**)&xhB, g_x_hi);
        cudaGetSymbolAddress((void**)&xlB, g_x_lo);
        cudaGetSymbolAddress((void**)&t1h, g_t1_hi);
        cudaGetSymbolAddress((void**)&t1l, g_t1_lo);
        cudaGetSymbolAddress((void**)&x,   g_x);
        cudaGetSymbolAddress((void**)&t2,  g_t2);
        cudaFuncSetAttribute((void*)(gemm_t)gemm_fp16<64, 32, 2, 2, 128, 6, 2>,
                             cudaFuncAttributeMaxDynamicSharedMemorySize, SMEM_SMALL);
        cudaFuncSetAttribute((void*)(gemm_t)gemm_fp16<128, 256, 4, 4, 512, 3, 1>,
                             cudaFuncAttributeMaxDynamicSharedMemorySize, SMEM_UNE);
        cudaStreamCreateWithFlags(&s2, cudaStreamNonBlocking);
        cudaEventCreateWithFlags(&evStart, cudaEventDisableTiming);
        cudaEventCreateWithFlags(&evDone,  cudaEventDisableTiming);
        for (int i = 0; i < HH; i++) cudaEventCreateWithFlags(&evH[i], cudaEventDisableTiming);
    }

    // fork s2 off the capture stream
    cudaEventRecord(evStart, 0);
    cudaStreamWaitEvent(s2, evStart, 0);

    // unembed weight conversion on s2 (only unembed consumes it)
    conv_w<<<2048, 256, 0, s2>>>(unemb_w, wh + OFF_UNE, 32768000 / 4);

    // chain weight conversions on main stream
    conv_w<<<1024, 256>>>(proj_w,  wh + OFF_PROJ, 8388608 / 4);
    conv_w<<<1024, 256>>>(sa_wv,   wh + OFF_SAWV, 4194304 / 4);
    conv_w<<<1024, 256>>>(sa_wo,   wh + OFF_SAWO, 4194304 / 4);
    conv_w<<<1024, 256>>>(ca_wv,   wh + OFF_CAWV, 4194304 / 4);
    conv_w<<<1024, 256>>>(ca_wo,   wh + OFF_CAWO, 4194304 / 4);
    conv_w<<<1024, 256>>>(ff_w1,   wh + OFF_FF1,  8388608 / 4);
    conv_w<<<1024, 256>>>(ff_w2,   wh + OFF_FF2,  8388608 / 4);

    init_h_kernel<<<MM, 256>>>(hidden, x);

    for (int h = 0; h < HH; h++) {
        __half *XH = xhB + (size_t)h * MM * DD;
        __half *XL = xlB + (size_t)h * MM * DD;

        prep_kernel<<<dim3(MM, 2), 256>>>(tok, emb, x, rms_w, xch, xcl, h);

        gemm_fp16<64, 32, 2, 2, 128, 6, 2><<<dim3(MM / 64, DD / 32), 128, SMEM_SMALL>>>(
            xch, xcl, wh + OFF_PROJ + (size_t)h * 2097152,
            proj_b + (size_t)h * DD, x, DD, XH, XL, DD, 2 * DD, 0);

        gemm_fp16<64, 32, 2, 2, 128, 6, 2><<<dim3(MM / 64, DD / 32), 128, SMEM_SMALL>>>(
            XH, XL, wh + OFF_SAWV + (size_t)h * 1048576,
            sa_bv + (size_t)h * DD, nullptr, 0, t1h, t1l, DD, DD, 0);
        gemm_fp16<64, 32, 2, 2, 128, 6, 2><<<dim3(MM / 64, DD / 32), 128, SMEM_SMALL>>>(
            t1h, t1l, wh + OFF_SAWO + (size_t)h * 1048576,
            sa_bo + (size_t)h * DD, t2, DD, nullptr, nullptr, 0, DD, 0);
        resid_ln_kernel<<<MM, 256>>>(x, t2, ln1_w + (size_t)h * DD, ln1_b + (size_t)h * DD, XH, XL);

        gemm_fp16<64, 32, 2, 2, 128, 6, 2><<<dim3(MM / 64, DD / 32), 128, SMEM_SMALL>>>(
            XH, XL, wh + OFF_CAWV + (size_t)h * 1048576,
            ca_bv + (size_t)h * DD, nullptr, 0, t1h, t1l, DD, DD, 0);
        gemm_fp16<64, 32, 2, 2, 128, 6, 2><<<dim3(MM / 64, DD / 32), 128, SMEM_SMALL>>>(
            t1h, t1l, wh + OFF_CAWO + (size_t)h * 1048576,
            ca_bo + (size_t)h * DD, t2, DD, nullptr, nullptr, 0, DD, 0);
        resid_ln_kernel<<<MM, 256>>>(x, t2, ln2_w + (size_t)h * DD, ln2_b + (size_t)h * DD, XH, XL);

        gemm_fp16<64, 32, 2, 2, 128, 6, 2><<<dim3(MM / 64, DFF / 32), 128, SMEM_SMALL>>>(
            XH, XL, wh + OFF_FF1 + (size_t)h * 2097152,
            ff_b1 + (size_t)h * DFF, nullptr, 0, t1h, t1l, DFF, DD, 1);
        gemm_fp16<64, 32, 2, 2, 128, 6, 2><<<dim3(MM / 64, DD / 32), 128, SMEM_SMALL>>>(
            t1h, t1l, wh + OFF_FF2 + (size_t)h * 2097152,
            ff_b2 + (size_t)h * DD, t2, DD, nullptr, nullptr, 0, DFF, 0);
        resid_ln_kernel<<<MM, 256>>>(x, t2, ln3_w + (size_t)h * DD, ln3_b + (size_t)h * DD, XH, XL);

        // hand final activations of head h to stream s2 for the unembed GEMM
        cudaEventRecord(evH[h], 0);
        cudaStreamWaitEvent(s2, evH[h], 0);
        gemm_fp16<128, 256, 4, 4, 512, 3, 1><<<dim3(MM / 128, VV / 256), 512, SMEM_UNE, s2>>>(
            XH, nullptr, wh + OFF_UNE,
            unemb_b, out + (size_t)h * VV, (long long)HH * VV, nullptr, nullptr, 0, DD, 0);
    }

    // join s2 back into the capture stream
    cudaEventRecord(evDone, s2);
    cudaStreamWaitEvent(0, evDone, 0);
}

// round 15
// speedup vs baseline: 1.1933x; 1.1933x over previous
#include <cuda_runtime.h>
#include <cuda_fp16.h>
#include <cstdint>

// Problem constants
#define BB   2
#define TT   260
#define HH   4
#define DD   1024
#define VV   32000
#define DFF  2048
#define MM   512

// ---------------------------------------------------------------------------
// Persistent scratch (__device__ globals; no allocations allowed)
// ---------------------------------------------------------------------------
#define OFF_PROJ 0
#define OFF_SAWV 8388608
#define OFF_SAWO 12582912
#define OFF_CAWV 16777216
#define OFF_CAWO 20971520
#define OFF_FF1  25165824
#define OFF_FF2  33554432
#define OFF_UNE  41943040
#define W_TOTAL  74711040

__device__ __half g_wh[W_TOTAL];                 // single-fp16 weights

__device__ float g_x  [MM * DD];
__device__ float g_t2 [MM * DD];
__device__ __half g_xc_hi[MM * 2 * DD], g_xc_lo[MM * 2 * DD];
__device__ __half g_x_hi [HH][MM * DD], g_x_lo [HH][MM * DD];  // per-head
__device__ __half g_t1_hi[MM * DFF],    g_t1_lo[MM * DFF];

// ---------------------------------------------------------------------------
// helpers
// ---------------------------------------------------------------------------
__device__ __forceinline__ float block_sum(float v) {
    __shared__ float sh[32];
    const int lane = threadIdx.x & 31;
    const int wid  = threadIdx.x >> 5;
    #pragma unroll
    for (int o = 16; o; o >>= 1) v += __shfl_xor_sync(0xffffffffu, v, o);
    if (lane == 0) sh[wid] = v;
    __syncthreads();
    if (wid == 0) {
        v = (lane < 8) ? sh[lane] : 0.0f;
        #pragma unroll
        for (int o = 4; o; o >>= 1) v += __shfl_xor_sync(0xffffffffu, v, o);
        if (lane == 0) sh[0] = v;
    }
    __syncthreads();
    v = sh[0];
    __syncthreads();
    return v;
}

__device__ __forceinline__ uint32_t s2u(const void* p) {
    uint32_t a;
    asm("{ .reg .u64 t; cvta.to.shared.u64 t, %1; cvt.u32.u64 %0, t; }" : "=r"(a) : "l"(p));
    return a;
}
__device__ __forceinline__ void ldsm4(uint32_t* r, uint32_t addr) {
    asm volatile("ldmatrix.sync.aligned.m8n8.x4.shared.b16 {%0,%1,%2,%3}, [%4];"
                 : "=r"(r[0]), "=r"(r[1]), "=r"(r[2]), "=r"(r[3]) : "r"(addr));
}
__device__ __forceinline__ void mma_f16(float* c, const uint32_t* a, const uint32_t* b) {
    asm volatile(
        "mma.sync.aligned.m16n8k16.row.col.f32.f16.f16.f32 "
        "{%0,%1,%2,%3}, {%4,%5,%6,%7}, {%8,%9}, {%0,%1,%2,%3};"
        : "+f"(c[0]), "+f"(c[1]), "+f"(c[2]), "+f"(c[3])
        : "r"(a[0]), "r"(a[1]), "r"(a[2]), "r"(a[3]), "r"(b[0]), "r"(b[1]));
}
__device__ __forceinline__ void split_h(float f, __half& h, __half& l) {
    h = __float2half_rn(f);
    l = __float2half_rn(f - __half2float(h));
}
__device__ __forceinline__ uint32_t pack_h2(__half a, __half b) {
    __half2 p = __halves2half2(a, b);
    return *reinterpret_cast<uint32_t*>(&p);
}

// ---------------------------------------------------------------------------
// weight conversion: fp32 -> single fp16
// ---------------------------------------------------------------------------
__global__ void conv_w(const float* __restrict__ src, __half* __restrict__ dst, int n4) {
    int i = blockIdx.x * blockDim.x + threadIdx.x;
    const int stride = gridDim.x * blockDim.x;
    for (; i < n4; i += stride) {
        float4 v = ((const float4*)src)[i];
        uint32_t p0 = pack_h2(__float2half_rn(v.x), __float2half_rn(v.y));
        uint32_t p1 = pack_h2(__float2half_rn(v.z), __float2half_rn(v.w));
        ((uint2*)dst)[i] = make_uint2(p0, p1);
    }
}

__global__ void init_h_kernel(const float* __restrict__ hidden, float* __restrict__ hbuf) {
    const int m = blockIdx.x;
    const int b = m >> 8, j = m & 255;
    const float* src = hidden + ((size_t)b * TT + j) * DD;
    float* dst = hbuf + (size_t)m * DD;
    #pragma unroll
    for (int i = 0; i < 4; i++) dst[threadIdx.x + i * 256] = src[threadIdx.x + i * 256];
}

__global__ void prep_kernel(const int* __restrict__ tok,
                            const float* __restrict__ emb,
                            const float* __restrict__ hprev,
                            const float* __restrict__ rms_w,
                            __half* __restrict__ xch,
                            __half* __restrict__ xcl, int h) {
    const int m = blockIdx.x;
    const int half = blockIdx.y;
    const int tid = threadIdx.x;
    const int b = m >> 8, j = m & 255;
    const float* src;
    if (half == 0) {
        const int t = tok[b * TT + 1 + h + j];
        src = emb + (size_t)t * DD;
    } else {
        src = hprev + (size_t)m * DD;
    }
    float v[4];
    float ss = 0.0f;
    #pragma unroll
    for (int i = 0; i < 4; i++) { v[i] = src[tid + i * 256]; ss += v[i] * v[i]; }
    ss = block_sum(ss);
    const float s = rsqrtf(ss * (1.0f / DD) + 1e-6f);
    const size_t base = (size_t)m * (2 * DD) + half * DD;
    #pragma unroll
    for (int i = 0; i < 4; i++) {
        const int d = tid + i * 256;
        const float f = v[i] * s * rms_w[d];
        __half hh, ll;
        split_h(f, hh, ll);
        xch[base + d] = hh;
        xcl[base + d] = ll;
    }
}

__global__ void resid_ln_kernel(float* __restrict__ x, const float* __restrict__ u,
                                const float* __restrict__ w, const float* __restrict__ bb,
                                __half* __restrict__ oh, __half* __restrict__ ol) {
    const int m = blockIdx.x;
    const int tid = threadIdx.x;
    float* xr = x + (size_t)m * DD;
    const float* ur = u + (size_t)m * DD;
    float v[4];
    float s = 0.0f;
    #pragma unroll
    for (int i = 0; i < 4; i++) {
        v[i] = xr[tid + i * 256] + ur[tid + i * 256];
        s += v[i];
    }
    s = block_sum(s);
    const float mu = s * (1.0f / DD);
    float s2 = 0.0f;
    #pragma unroll
    for (int i = 0; i < 4; i++) { const float d = v[i] - mu; s2 += d * d; }
    s2 = block_sum(s2);
    const float rs = rsqrtf(s2 * (1.0f / DD) + 1e-5f);
    #pragma unroll
    for (int i = 0; i < 4; i++) {
        const int d = tid + i * 256;
        const float f = (v[i] - mu) * rs * w[d] + bb[d];
        xr[d] = f;
        __half hh, ll;
        split_h(f, hh, ll);
        oh[(size_t)m * DD + d] = hh;
        ol[(size_t)m * DD + d] = ll;
    }
}

// ---------------------------------------------------------------------------
// fp16 GEMM: C[m,n] = sum_k A[m,k]*B[n,k] + bias[n]
// NPROD=2: A = (Ahi + Alo) fp16 hi/lo pair   (chain)
// NPROD=1: A = Ahi only                      (unembed)
// BK-elem K-chunks; LS = BK+8 padded rows (row stride = 2*LS bytes = n*16,
// and ≡16 mod 128 -> conflict-free ldsm).
// ---------------------------------------------------------------------------
template<int BM, int BN, int WGM, int WGN, int NTH, int S, int NPROD, int BK>
__global__ void __launch_bounds__(NTH) gemm_fp16(
    const __half* __restrict__ Ahi, const __half* __restrict__ Alo,
    const __half* __restrict__ Bh,
    const float* __restrict__ bias,
    float* __restrict__ C, long long ldc,
    __half* __restrict__ Ohi, __half* __restrict__ Olo, int ldo,
    int K, int relu)
{
    constexpr int WM  = BM / WGM;
    constexpr int WN  = BN / WGN;
    constexpr int MI  = WM / 16;
    constexpr int NI  = WN / 8;
    constexpr int LS  = BK + 8;
    constexpr int CPR = BK / 8;            // 16B loads per row
    constexpr int AT  = BM * LS * 2;
    constexpr int BT  = BN * LS * 2;
    constexpr int STAGE = NPROD * AT + BT;
    constexpr int NKS = BK / 16;

    extern __shared__ char smem[];
    const uint32_t sb = s2u(smem);

    const int tid  = threadIdx.x;
    const int wid  = tid >> 5;
    const int lane = tid & 31;
    const int wm   = wid / WGN;
    const int wn   = wid % WGN;
    const int m0   = blockIdx.x * BM;
    const int n0   = blockIdx.y * BN;
    const int nCh  = K / BK;

    float acc[MI][NI][4];
    #pragma unroll
    for (int i = 0; i < MI; i++)
        #pragma unroll
        for (int j = 0; j < NI; j++)
            #pragma unroll
            for (int q = 0; q < 4; q++) acc[i][j][q] = 0.0f;

    auto issue = [&](int c) {
        if (c < nCh) {
            const int k0 = c * BK;
            const uint32_t st = sb + (uint32_t)(c % S) * STAGE;
            #pragma unroll
            for (int q = tid; q < BM * CPR; q += NTH) {
                const int row = q / CPR, col = (q % CPR) * 8;
                const size_t off = (size_t)(m0 + row) * K + k0 + col;
                const uint32_t d = st + (uint32_t)(row * LS + col) * 2u;
                asm volatile("cp.async.cg.shared.global [%0], [%1], 16;" :: "r"(d), "l"(Ahi + off));
                if (NPROD == 2)
                    asm volatile("cp.async.cg.shared.global [%0], [%1], 16;" :: "r"(d + AT), "l"(Alo + off));
            }
            #pragma unroll
            for (int q = tid; q < BN * CPR; q += NTH) {
                const int row = q / CPR, col = (q % CPR) * 8;
                const size_t off = (size_t)(n0 + row) * K + k0 + col;
                const uint32_t d = st + NPROD * AT + (uint32_t)(row * LS + col) * 2u;
                asm volatile("cp.async.cg.shared.global [%0], [%1], 16;" :: "r"(d), "l"(Bh + off));
            }
        }
        asm volatile("cp.async.commit_group;" ::: "memory");
    };

    #pragma unroll
    for (int p = 0; p < S - 1; p++) issue(p);

    for (int c = 0; c < nCh; c++) {
        asm volatile("cp.async.wait_group %0;" :: "n"(S - 2) : "memory");
        __syncthreads();
        issue(c + S - 1);

        const uint32_t st  = sb + (uint32_t)(c % S) * STAGE;
        const uint32_t sAh = st;
        const uint32_t sBh = st + NPROD * AT;
        #pragma unroll
        for (int ks = 0; ks < NKS; ks++) {
            uint32_t ah[MI][4], al[MI][4];
            #pragma unroll
            for (int mi = 0; mi < MI; mi++) {
                const int row = wm * WM + mi * 16 + (lane & 15);
                const int col = ks * 16 + (lane >> 4) * 8;
                const uint32_t ad = sAh + (uint32_t)(row * LS + col) * 2u;
                ldsm4(ah[mi], ad);
                if (NPROD == 2) ldsm4(al[mi], ad + AT);
            }
            uint32_t bh[NI][2];
            #pragma unroll
            for (int ni = 0; ni < NI; ni += 2) {
                const int g = lane >> 3;
                const int row = wn * WN + ni * 8 + ((g >> 1) << 3) + (lane & 7);
                const int col = ks * 16 + ((g & 1) << 3);
                const uint32_t bd = sBh + (uint32_t)(row * LS + col) * 2u;
                ldsm4(&bh[ni][0], bd);
            }
            #pragma unroll
            for (int mi = 0; mi < MI; mi++)
                #pragma unroll
                for (int ni = 0; ni < NI; ni++)
                    mma_f16(acc[mi][ni], ah[mi], bh[ni]);
            if (NPROD == 2) {
                #pragma unroll
                for (int mi = 0; mi < MI; mi++)
                    #pragma unroll
                    for (int ni = 0; ni < NI; ni++)
                        mma_f16(acc[mi][ni], al[mi], bh[ni]);
            }
        }
    }

    #pragma unroll
    for (int mi = 0; mi < MI; mi++) {
        #pragma unroll
        for (int ni = 0; ni < NI; ni++) {
            const int r0 = m0 + wm * WM + mi * 16 + (lane >> 2);
            const int cc = n0 + wn * WN + ni * 8 + ((lane & 3) << 1);
            const float b0 = bias[cc], b1 = bias[cc + 1];
            float v0 = acc[mi][ni][0] + b0;
            float v1 = acc[mi][ni][1] + b1;
            float v2 = acc[mi][ni][2] + b0;
            float v3 = acc[mi][ni][3] + b1;
            if (relu) {
                v0 = fmaxf(v0, 0.0f); v1 = fmaxf(v1, 0.0f);
                v2 = fmaxf(v2, 0.0f); v3 = fmaxf(v3, 0.0f);
            }
            if (C) {
                *(float2*)(C + (size_t)r0 * (size_t)ldc + cc)       = make_float2(v0, v1);
                *(float2*)(C + (size_t)(r0 + 8) * (size_t)ldc + cc) = make_float2(v2, v3);
            }
            if (Ohi) {
                __half h0, l0, h1, l1, h2, l2, h3, l3;
                split_h(v0, h0, l0); split_h(v1, h1, l1);
                split_h(v2, h2, l2); split_h(v3, h3, l3);
                *(uint32_t*)(Ohi + (size_t)r0 * ldo + cc)       = pack_h2(h0, h1);
                *(uint32_t*)(Olo + (size_t)r0 * ldo + cc)       = pack_h2(l0, l1);
                *(uint32_t*)(Ohi + (size_t)(r0 + 8) * ldo + cc) = pack_h2(h2, h3);
                *(uint32_t*)(Olo + (size_t)(r0 + 8) * ldo + cc) = pack_h2(l2, l3);
            }
        }
    }
}

// chain: 64x64, 8 warps (WGM=2,WGN=4), BK=64, NPROD=2, S=3.
// stage = (2*64+64)*72*2 = 27648 -> 82944 B
#define SMEM_SMALL (3 * ((2 * 64 + 64) * 72 * 2))
// unembed: 128x256, BK=32, NPROD=1, S=4 -> 4*(128+256)*40*2 = 122880 B
#define SMEM_UNE   (4 * ((128 + 256) * 40 * 2))

typedef void (*gemm_t)(const __half*, const __half*, const __half*,
                       const float*, float*, long long,
                       __half*, __half*, int, int, int);

// ---------------------------------------------------------------------------
// Host orchestration
// ---------------------------------------------------------------------------
extern "C" void kernel_launch(void* const* d_in, const int* in_sizes, int n_in,
                              void* d_out, int out_size) {
    const int*   tok     = (const int*)  d_in[0];
    const float* hidden  = (const float*)d_in[1];
    const float* emb     = (const float*)d_in[2];
    const float* rms_w   = (const float*)d_in[3];
    const float* proj_w  = (const float*)d_in[4];
    const float* proj_b  = (const float*)d_in[5];
    const float* sa_wv   = (const float*)d_in[6];
    const float* sa_bv   = (const float*)d_in[7];
    const float* sa_wo   = (const float*)d_in[8];
    const float* sa_bo   = (const float*)d_in[9];
    const float* ca_wv   = (const float*)d_in[10];
    const float* ca_bv   = (const float*)d_in[11];
    const float* ca_wo   = (const float*)d_in[12];
    const float* ca_bo   = (const float*)d_in[13];
    const float* ln1_w   = (const float*)d_in[14];
    const float* ln1_b   = (const float*)d_in[15];
    const float* ln2_w   = (const float*)d_in[16];
    const float* ln2_b   = (const float*)d_in[17];
    const float* ln3_w   = (const float*)d_in[18];
    const float* ln3_b   = (const float*)d_in[19];
    const float* ff_w1   = (const float*)d_in[20];
    const float* ff_b1   = (const float*)d_in[21];
    const float* ff_w2   = (const float*)d_in[22];
    const float* ff_b2   = (const float*)d_in[23];
    const float* unemb_w = (const float*)d_in[24];
    const float* unemb_b = (const float*)d_in[25];
    float* out = (float*)d_out;

    static __half *wh = nullptr;
    static __half *xch = nullptr, *xcl = nullptr;
    static __half *xhB = nullptr, *xlB = nullptr;
    static __half *t1h = nullptr, *t1l = nullptr;
    static float *x = nullptr, *t2 = nullptr;
    static cudaStream_t s2 = nullptr;
    static cudaEvent_t evStart = nullptr, evDone = nullptr, evH[HH] = {};
    if (!wh) {
        cudaGetSymbolAddress((void**)&wh,  g_wh);
        cudaGetSymbolAddress((void**)&xch, g_xc_hi);
        cudaGetSymbolAddress((void**)&xcl, g_xc_lo);
        cudaGetSymbolAddress((void**)&xhB, g_x_hi);
        cudaGetSymbolAddress((void**)&xlB, g_x_lo);
        cudaGetSymbolAddress((void**)&t1h, g_t1_hi);
        cudaGetSymbolAddress((void**)&t1l, g_t1_lo);
        cudaGetSymbolAddress((void**)&x,   g_x);
        cudaGetSymbolAddress((void**)&t2,  g_t2);
        cudaFuncSetAttribute((void*)(gemm_t)gemm_fp16<64, 64, 2, 4, 256, 3, 2, 64>,
                             cudaFuncAttributeMaxDynamicSharedMemorySize, SMEM_SMALL);
        cudaFuncSetAttribute((void*)(gemm_t)gemm_fp16<128, 256, 4, 4, 512, 4, 1, 32>,
                             cudaFuncAttributeMaxDynamicSharedMemorySize, SMEM_UNE);
        cudaStreamCreateWithFlags(&s2, cudaStreamNonBlocking);
        cudaEventCreateWithFlags(&evStart, cudaEventDisableTiming);
        cudaEventCreateWithFlags(&evDone,  cudaEventDisableTiming);
        for (int i = 0; i < HH; i++) cudaEventCreateWithFlags(&evH[i], cudaEventDisableTiming);
    }

    // fork s2 off the capture stream
    cudaEventRecord(evStart, 0);
    cudaStreamWaitEvent(s2, evStart, 0);

    // unembed weight conversion on s2 (only unembed consumes it)
    conv_w<<<2048, 256, 0, s2>>>(unemb_w, wh + OFF_UNE, 32768000 / 4);

    // chain weight conversions on main stream
    conv_w<<<1024, 256>>>(proj_w,  wh + OFF_PROJ, 8388608 / 4);
    conv_w<<<1024, 256>>>(sa_wv,   wh + OFF_SAWV, 4194304 / 4);
    conv_w<<<1024, 256>>>(sa_wo,   wh + OFF_SAWO, 4194304 / 4);
    conv_w<<<1024, 256>>>(ca_wv,   wh + OFF_CAWV, 4194304 / 4);
    conv_w<<<1024, 256>>>(ca_wo,   wh + OFF_CAWO, 4194304 / 4);
    conv_w<<<1024, 256>>>(ff_w1,   wh + OFF_FF1,  8388608 / 4);
    conv_w<<<1024, 256>>>(ff_w2,   wh + OFF_FF2,  8388608 / 4);

    init_h_kernel<<<MM, 256>>>(hidden, x);

    for (int h = 0; h < HH; h++) {
        __half *XH = xhB + (size_t)h * MM * DD;
        __half *XL = xlB + (size_t)h * MM * DD;

        prep_kernel<<<dim3(MM, 2), 256>>>(tok, emb, x, rms_w, xch, xcl, h);

        gemm_fp16<64, 64, 2, 4, 256, 3, 2, 64><<<dim3(MM / 64, DD / 64), 256, SMEM_SMALL>>>(
            xch, xcl, wh + OFF_PROJ + (size_t)h * 2097152,
            proj_b + (size_t)h * DD, x, DD, XH, XL, DD, 2 * DD, 0);

        gemm_fp16<64, 64, 2, 4, 256, 3, 2, 64><<<dim3(MM / 64, DD / 64), 256, SMEM_SMALL>>>(
            XH, XL, wh + OFF_SAWV + (size_t)h * 1048576,
            sa_bv + (size_t)h * DD, nullptr, 0, t1h, t1l, DD, DD, 0);
        gemm_fp16<64, 64, 2, 4, 256, 3, 2, 64><<<dim3(MM / 64, DD / 64), 256, SMEM_SMALL>>>(
            t1h, t1l, wh + OFF_SAWO + (size_t)h * 1048576,
            sa_bo + (size_t)h * DD, t2, DD, nullptr, nullptr, 0, DD, 0);
        resid_ln_kernel<<<MM, 256>>>(x, t2, ln1_w + (size_t)h * DD, ln1_b + (size_t)h * DD, XH, XL);

        gemm_fp16<64, 64, 2, 4, 256, 3, 2, 64><<<dim3(MM / 64, DD / 64), 256, SMEM_SMALL>>>(
            XH, XL, wh + OFF_CAWV + (size_t)h * 1048576,
            ca_bv + (size_t)h * DD, nullptr, 0, t1h, t1l, DD, DD, 0);
        gemm_fp16<64, 64, 2, 4, 256, 3, 2, 64><<<dim3(MM / 64, DD / 64), 256, SMEM_SMALL>>>(
            t1h, t1l, wh + OFF_CAWO + (size_t)h * 1048576,
            ca_bo + (size_t)h * DD, t2, DD, nullptr, nullptr, 0, DD, 0);
        resid_ln_kernel<<<MM, 256>>>(x, t2, ln2_w + (size_t)h * DD, ln2_b + (size_t)h * DD, XH, XL);

        gemm_fp16<64, 64, 2, 4, 256, 3, 2, 64><<<dim3(MM / 64, DFF / 64), 256, SMEM_SMALL>>>(
            XH, XL, wh + OFF_FF1 + (size_t)h * 2097152,
            ff_b1 + (size_t)h * DFF, nullptr, 0, t1h, t1l, DFF, DD, 1);
        gemm_fp16<64, 64, 2, 4, 256, 3, 2, 64><<<dim3(MM / 64, DD / 64), 256, SMEM_SMALL>>>(
            t1h, t1l, wh + OFF_FF2 + (size_t)h * 2097152,
            ff_b2 + (size_t)h * DD, t2, DD, nullptr, nullptr, 0, DFF, 0);
        resid_ln_kernel<<<MM, 256>>>(x, t2, ln3_w + (size_t)h * DD, ln3_b + (size_t)h * DD, XH, XL);

        // hand final activations of head h to stream s2 for the unembed GEMM
        cudaEventRecord(evH[h], 0);
        cudaStreamWaitEvent(s2, evH[h], 0);
        gemm_fp16<128, 256, 4, 4, 512, 4, 1, 32><<<dim3(MM / 128, VV / 256), 512, SMEM_UNE, s2>>>(
            XH, nullptr, wh + OFF_UNE,
            unemb_b, out + (size_t)h * VV, (long long)HH * VV, nullptr, nullptr, 0, DD, 0);
    }

    // join s2 back into the capture stream
    cudaEventRecord(evDone, s2);
    cudaStreamWaitEvent(0, evDone, 0);
}

// round 16
// speedup vs baseline: 1.2345x; 1.0345x over previous
#include <cuda_runtime.h>
#include <cuda_fp16.h>
#include <cstdint>

// Problem constants
#define BB   2
#define TT   260
#define HH   4
#define DD   1024
#define VV   32000
#define DFF  2048
#define MM   512

// ---------------------------------------------------------------------------
// Persistent scratch (__device__ globals; no allocations allowed)
// ---------------------------------------------------------------------------
#define OFF_PROJ 0
#define OFF_SAWO 8388608
#define OFF_CAWO 12582912
#define OFF_FF1  16777216
#define OFF_FF2  25165824
#define OFF_UNE  33554432
#define W_TOTAL  66322432

__device__ __half g_wh[W_TOTAL];                 // fp16 weights (conv'd per launch)
__device__ __half g_wcomb[8 * DD * DD];          // combined sa/ca weights: [2h]=sa, [2h+1]=ca
__device__ float  g_b2[8 * DD];                  // combined biases
__device__ __half g_wvT[DD * DD];                // transpose scratch (s3-serial)
__device__ float  g_zero[DFF];                   // zero bias (static zero-init)

__device__ float g_x  [MM * DD];
__device__ float g_t2 [MM * DD];
__device__ __half g_xc_hi[MM * 2 * DD], g_xc_lo[MM * 2 * DD];
__device__ __half g_x_hi [HH][MM * DD], g_x_lo [HH][MM * DD];  // per-head
__device__ __half g_t1_hi[MM * DFF],    g_t1_lo[MM * DFF];

// ---------------------------------------------------------------------------
// helpers
// ---------------------------------------------------------------------------
__device__ __forceinline__ float block_sum(float v) {
    __shared__ float sh[32];
    const int lane = threadIdx.x & 31;
    const int wid  = threadIdx.x >> 5;
    #pragma unroll
    for (int o = 16; o; o >>= 1) v += __shfl_xor_sync(0xffffffffu, v, o);
    if (lane == 0) sh[wid] = v;
    __syncthreads();
    if (wid == 0) {
        v = (lane < 8) ? sh[lane] : 0.0f;
        #pragma unroll
        for (int o = 4; o; o >>= 1) v += __shfl_xor_sync(0xffffffffu, v, o);
        if (lane == 0) sh[0] = v;
    }
    __syncthreads();
    v = sh[0];
    __syncthreads();
    return v;
}

__device__ __forceinline__ uint32_t s2u(const void* p) {
    uint32_t a;
    asm("{ .reg .u64 t; cvta.to.shared.u64 t, %1; cvt.u32.u64 %0, t; }" : "=r"(a) : "l"(p));
    return a;
}
__device__ __forceinline__ void ldsm4(uint32_t* r, uint32_t addr) {
    asm volatile("ldmatrix.sync.aligned.m8n8.x4.shared.b16 {%0,%1,%2,%3}, [%4];"
                 : "=r"(r[0]), "=r"(r[1]), "=r"(r[2]), "=r"(r[3]) : "r"(addr));
}
__device__ __forceinline__ void mma_f16(float* c, const uint32_t* a, const uint32_t* b) {
    asm volatile(
        "mma.sync.aligned.m16n8k16.row.col.f32.f16.f16.f32 "
        "{%0,%1,%2,%3}, {%4,%5,%6,%7}, {%8,%9}, {%0,%1,%2,%3};"
        : "+f"(c[0]), "+f"(c[1]), "+f"(c[2]), "+f"(c[3])
        : "r"(a[0]), "r"(a[1]), "r"(a[2]), "r"(a[3]), "r"(b[0]), "r"(b[1]));
}
__device__ __forceinline__ void split_h(float f, __half& h, __half& l) {
    h = __float2half_rn(f);
    l = __float2half_rn(f - __half2float(h));
}
__device__ __forceinline__ uint32_t pack_h2(__half a, __half b) {
    __half2 p = __halves2half2(a, b);
    return *reinterpret_cast<uint32_t*>(&p);
}

// ---------------------------------------------------------------------------
// weight conversion: fp32 -> single fp16
// ---------------------------------------------------------------------------
__global__ void conv_w(const float* __restrict__ src, __half* __restrict__ dst, int n4) {
    int i = blockIdx.x * blockDim.x + threadIdx.x;
    const int stride = gridDim.x * blockDim.x;
    for (; i < n4; i += stride) {
        float4 v = ((const float4*)src)[i];
        uint32_t p0 = pack_h2(__float2half_rn(v.x), __float2half_rn(v.y));
        uint32_t p1 = pack_h2(__float2half_rn(v.z), __float2half_rn(v.w));
        ((uint2*)dst)[i] = make_uint2(p0, p1);
    }
}

// transpose + convert: dst[k][n] = fp16(src[n][k]), DxD
__global__ void transp_kernel(const float* __restrict__ src, __half* __restrict__ dst) {
    __shared__ float tile[32][33];
    const int n0 = blockIdx.x * 32, k0 = blockIdx.y * 32;
    for (int i = threadIdx.y; i < 32; i += 8)
        tile[i][threadIdx.x] = src[(size_t)(n0 + i) * DD + k0 + threadIdx.x];
    __syncthreads();
    for (int i = threadIdx.y; i < 32; i += 8)
        dst[(size_t)(k0 + i) * DD + n0 + threadIdx.x] = __float2half_rn(tile[threadIdx.x][i]);
}

// b2[p] = bo[p] + dot(wo[p,:], bv)  — one warp per p
__global__ void comb_bias_kernel(const float* __restrict__ wo, const float* __restrict__ bv,
                                 const float* __restrict__ bo, float* __restrict__ b2) {
    const int w = threadIdx.x >> 5, lane = threadIdx.x & 31;
    const int p = blockIdx.x * 8 + w;
    const float* row = wo + (size_t)p * DD;
    float s = 0.0f;
    for (int n = lane; n < DD; n += 32) s += row[n] * bv[n];
    #pragma unroll
    for (int o = 16; o; o >>= 1) s += __shfl_xor_sync(0xffffffffu, s, o);
    if (lane == 0) b2[p] = s + bo[p];
}

__global__ void init_h_kernel(const float* __restrict__ hidden, float* __restrict__ hbuf) {
    const int m = blockIdx.x;
    const int b = m >> 8, j = m & 255;
    const float* src = hidden + ((size_t)b * TT + j) * DD;
    float* dst = hbuf + (size_t)m * DD;
    #pragma unroll
    for (int i = 0; i < 4; i++) dst[threadIdx.x + i * 256] = src[threadIdx.x + i * 256];
}

__global__ void prep_kernel(const int* __restrict__ tok,
                            const float* __restrict__ emb,
                            const float* __restrict__ hprev,
                            const float* __restrict__ rms_w,
                            __half* __restrict__ xch,
                            __half* __restrict__ xcl, int h) {
    const int m = blockIdx.x;
    const int half = blockIdx.y;
    const int tid = threadIdx.x;
    const int b = m >> 8, j = m & 255;
    const float* src;
    if (half == 0) {
        const int t = tok[b * TT + 1 + h + j];
        src = emb + (size_t)t * DD;
    } else {
        src = hprev + (size_t)m * DD;
    }
    float v[4];
    float ss = 0.0f;
    #pragma unroll
    for (int i = 0; i < 4; i++) { v[i] = src[tid + i * 256]; ss += v[i] * v[i]; }
    ss = block_sum(ss);
    const float s = rsqrtf(ss * (1.0f / DD) + 1e-6f);
    const size_t base = (size_t)m * (2 * DD) + half * DD;
    #pragma unroll
    for (int i = 0; i < 4; i++) {
        const int d = tid + i * 256;
        const float f = v[i] * s * rms_w[d];
        __half hh, ll;
        split_h(f, hh, ll);
        xch[base + d] = hh;
        xcl[base + d] = ll;
    }
}

__global__ void resid_ln_kernel(float* __restrict__ x, const float* __restrict__ u,
                                const float* __restrict__ w, const float* __restrict__ bb,
                                __half* __restrict__ oh, __half* __restrict__ ol) {
    const int m = blockIdx.x;
    const int tid = threadIdx.x;
    float* xr = x + (size_t)m * DD;
    const float* ur = u + (size_t)m * DD;
    float v[4];
    float s = 0.0f;
    #pragma unroll
    for (int i = 0; i < 4; i++) {
        v[i] = xr[tid + i * 256] + ur[tid + i * 256];
        s += v[i];
    }
    s = block_sum(s);
    const float mu = s * (1.0f / DD);
    float s2 = 0.0f;
    #pragma unroll
    for (int i = 0; i < 4; i++) { const float d = v[i] - mu; s2 += d * d; }
    s2 = block_sum(s2);
    const float rs = rsqrtf(s2 * (1.0f / DD) + 1e-5f);
    #pragma unroll
    for (int i = 0; i < 4; i++) {
        const int d = tid + i * 256;
        const float f = (v[i] - mu) * rs * w[d] + bb[d];
        xr[d] = f;
        __half hh, ll;
        split_h(f, hh, ll);
        oh[(size_t)m * DD + d] = hh;
        ol[(size_t)m * DD + d] = ll;
    }
}

// ---------------------------------------------------------------------------
// fp16 GEMM: C[m,n] = sum_k A[m,k]*B[n,k] + bias[n]
// NPROD=2: A = (Ahi + Alo) fp16 hi/lo pair; NPROD=1: A = Ahi only.
// Ohi set, Olo null -> single fp16 output (combined-weight path).
// ---------------------------------------------------------------------------
template<int BM, int BN, int WGM, int WGN, int NTH, int S, int NPROD, int BK>
__global__ void __launch_bounds__(NTH) gemm_fp16(
    const __half* __restrict__ Ahi, const __half* __restrict__ Alo,
    const __half* __restrict__ Bh,
    const float* __restrict__ bias,
    float* __restrict__ C, long long ldc,
    __half* __restrict__ Ohi, __half* __restrict__ Olo, int ldo,
    int K, int relu)
{
    constexpr int WM  = BM / WGM;
    constexpr int WN  = BN / WGN;
    constexpr int MI  = WM / 16;
    constexpr int NI  = WN / 8;
    constexpr int LS  = BK + 8;
    constexpr int CPR = BK / 8;
    constexpr int AT  = BM * LS * 2;
    constexpr int BT  = BN * LS * 2;
    constexpr int STAGE = NPROD * AT + BT;
    constexpr int NKS = BK / 16;

    extern __shared__ char smem[];
    const uint32_t sb = s2u(smem);

    const int tid  = threadIdx.x;
    const int wid  = tid >> 5;
    const int lane = tid & 31;
    const int wm   = wid / WGN;
    const int wn   = wid % WGN;
    const int m0   = blockIdx.x * BM;
    const int n0   = blockIdx.y * BN;
    const int nCh  = K / BK;

    float acc[MI][NI][4];
    #pragma unroll
    for (int i = 0; i < MI; i++)
        #pragma unroll
        for (int j = 0; j < NI; j++)
            #pragma unroll
            for (int q = 0; q < 4; q++) acc[i][j][q] = 0.0f;

    auto issue = [&](int c) {
        if (c < nCh) {
            const int k0 = c * BK;
            const uint32_t st = sb + (uint32_t)(c % S) * STAGE;
            #pragma unroll
            for (int q = tid; q < BM * CPR; q += NTH) {
                const int row = q / CPR, col = (q % CPR) * 8;
                const size_t off = (size_t)(m0 + row) * K + k0 + col;
                const uint32_t d = st + (uint32_t)(row * LS + col) * 2u;
                asm volatile("cp.async.cg.shared.global [%0], [%1], 16;" :: "r"(d), "l"(Ahi + off));
                if (NPROD == 2)
                    asm volatile("cp.async.cg.shared.global [%0], [%1], 16;" :: "r"(d + AT), "l"(Alo + off));
            }
            #pragma unroll
            for (int q = tid; q < BN * CPR; q += NTH) {
                const int row = q / CPR, col = (q % CPR) * 8;
                const size_t off = (size_t)(n0 + row) * K + k0 + col;
                const uint32_t d = st + NPROD * AT + (uint32_t)(row * LS + col) * 2u;
                asm volatile("cp.async.cg.shared.global [%0], [%1], 16;" :: "r"(d), "l"(Bh + off));
            }
        }
        asm volatile("cp.async.commit_group;" ::: "memory");
    };

    #pragma unroll
    for (int p = 0; p < S - 1; p++) issue(p);

    for (int c = 0; c < nCh; c++) {
        asm volatile("cp.async.wait_group %0;" :: "n"(S - 2) : "memory");
        __syncthreads();
        issue(c + S - 1);

        const uint32_t st  = sb + (uint32_t)(c % S) * STAGE;
        const uint32_t sAh = st;
        const uint32_t sBh = st + NPROD * AT;
        #pragma unroll
        for (int ks = 0; ks < NKS; ks++) {
            uint32_t ah[MI][4], al[MI][4];
            #pragma unroll
            for (int mi = 0; mi < MI; mi++) {
                const int row = wm * WM + mi * 16 + (lane & 15);
                const int col = ks * 16 + (lane >> 4) * 8;
                const uint32_t ad = sAh + (uint32_t)(row * LS + col) * 2u;
                ldsm4(ah[mi], ad);
                if (NPROD == 2) ldsm4(al[mi], ad + AT);
            }
            uint32_t bh[NI][2];
            #pragma unroll
            for (int ni = 0; ni < NI; ni += 2) {
                const int g = lane >> 3;
                const int row = wn * WN + ni * 8 + ((g >> 1) << 3) + (lane & 7);
                const int col = ks * 16 + ((g & 1) << 3);
                const uint32_t bd = sBh + (uint32_t)(row * LS + col) * 2u;
                ldsm4(&bh[ni][0], bd);
            }
            #pragma unroll
            for (int mi = 0; mi < MI; mi++)
                #pragma unroll
                for (int ni = 0; ni < NI; ni++)
                    mma_f16(acc[mi][ni], ah[mi], bh[ni]);
            if (NPROD == 2) {
                #pragma unroll
                for (int mi = 0; mi < MI; mi++)
                    #pragma unroll
                    for (int ni = 0; ni < NI; ni++)
                        mma_f16(acc[mi][ni], al[mi], bh[ni]);
            }
        }
    }

    #pragma unroll
    for (int mi = 0; mi < MI; mi++) {
        #pragma unroll
        for (int ni = 0; ni < NI; ni++) {
            const int r0 = m0 + wm * WM + mi * 16 + (lane >> 2);
            const int cc = n0 + wn * WN + ni * 8 + ((lane & 3) << 1);
            const float b0 = bias[cc], b1 = bias[cc + 1];
            float v0 = acc[mi][ni][0] + b0;
            float v1 = acc[mi][ni][1] + b1;
            float v2 = acc[mi][ni][2] + b0;
            float v3 = acc[mi][ni][3] + b1;
            if (relu) {
                v0 = fmaxf(v0, 0.0f); v1 = fmaxf(v1, 0.0f);
                v2 = fmaxf(v2, 0.0f); v3 = fmaxf(v3, 0.0f);
            }
            if (C) {
                *(float2*)(C + (size_t)r0 * (size_t)ldc + cc)       = make_float2(v0, v1);
                *(float2*)(C + (size_t)(r0 + 8) * (size_t)ldc + cc) = make_float2(v2, v3);
            }
            if (Ohi) {
                __half h0, l0, h1, l1, h2, l2, h3, l3;
                split_h(v0, h0, l0); split_h(v1, h1, l1);
                split_h(v2, h2, l2); split_h(v3, h3, l3);
                *(uint32_t*)(Ohi + (size_t)r0 * ldo + cc)       = pack_h2(h0, h1);
                *(uint32_t*)(Ohi + (size_t)(r0 + 8) * ldo + cc) = pack_h2(h2, h3);
                if (Olo) {
                    *(uint32_t*)(Olo + (size_t)r0 * ldo + cc)       = pack_h2(l0, l1);
                    *(uint32_t*)(Olo + (size_t)(r0 + 8) * ldo + cc) = pack_h2(l2, l3);
                }
            }
        }
    }
}

// chain: 64x64, BK=64, NPROD=2, S=3 -> 3*(2*64+64)*72*2 = 82944 B
#define SMEM_SMALL (3 * ((2 * 64 + 64) * 72 * 2))
// combine: 64x64, BK=64, NPROD=1, S=3 -> 3*(64+64)*72*2 = 55296 B
#define SMEM_COMB  (3 * ((64 + 64) * 72 * 2))
// unembed: 128x256, BK=32, NPROD=1, S=4 -> 4*(128+256)*40*2 = 122880 B
#define SMEM_UNE   (4 * ((128 + 256) * 40 * 2))

typedef void (*gemm_t)(const __half*, const __half*, const __half*,
                       const float*, float*, long long,
                       __half*, __half*, int, int, int);

// ---------------------------------------------------------------------------
// Host orchestration
// ---------------------------------------------------------------------------
extern "C" void kernel_launch(void* const* d_in, const int* in_sizes, int n_in,
                              void* d_out, int out_size) {
    const int*   tok     = (const int*)  d_in[0];
    const float* hidden  = (const float*)d_in[1];
    const float* emb     = (const float*)d_in[2];
    const float* rms_w   = (const float*)d_in[3];
    const float* proj_w  = (const float*)d_in[4];
    const float* proj_b  = (const float*)d_in[5];
    const float* sa_wv   = (const float*)d_in[6];
    const float* sa_bv   = (const float*)d_in[7];
    const float* sa_wo   = (const float*)d_in[8];
    const float* sa_bo   = (const float*)d_in[9];
    const float* ca_wv   = (const float*)d_in[10];
    const float* ca_bv   = (const float*)d_in[11];
    const float* ca_wo   = (const float*)d_in[12];
    const float* ca_bo   = (const float*)d_in[13];
    const float* ln1_w   = (const float*)d_in[14];
    const float* ln1_b   = (const float*)d_in[15];
    const float* ln2_w   = (const float*)d_in[16];
    const float* ln2_b   = (const float*)d_in[17];
    const float* ln3_w   = (const float*)d_in[18];
    const float* ln3_b   = (const float*)d_in[19];
    const float* ff_w1   = (const float*)d_in[20];
    const float* ff_b1   = (const float*)d_in[21];
    const float* ff_w2   = (const float*)d_in[22];
    const float* ff_b2   = (const float*)d_in[23];
    const float* unemb_w = (const float*)d_in[24];
    const float* unemb_b = (const float*)d_in[25];
    float* out = (float*)d_out;

    static __half *wh = nullptr, *wcomb = nullptr, *wvT = nullptr;
    static float  *b2 = nullptr, *zero = nullptr;
    static __half *xch = nullptr, *xcl = nullptr;
    static __half *xhB = nullptr, *xlB = nullptr;
    static __half *t1h = nullptr, *t1l = nullptr;
    static float *x = nullptr, *t2 = nullptr;
    static cudaStream_t s2 = nullptr, s3 = nullptr;
    static cudaEvent_t evStart = nullptr, evDone = nullptr;
    static cudaEvent_t evH[HH] = {}, evSA[HH] = {}, evCA[HH] = {};
    if (!wh) {
        cudaGetSymbolAddress((void**)&wh,    g_wh);
        cudaGetSymbolAddress((void**)&wcomb, g_wcomb);
        cudaGetSymbolAddress((void**)&wvT,   g_wvT);
        cudaGetSymbolAddress((void**)&b2,    g_b2);
        cudaGetSymbolAddress((void**)&zero,  g_zero);
        cudaGetSymbolAddress((void**)&xch,   g_xc_hi);
        cudaGetSymbolAddress((void**)&xcl,   g_xc_lo);
        cudaGetSymbolAddress((void**)&xhB,   g_x_hi);
        cudaGetSymbolAddress((void**)&xlB,   g_x_lo);
        cudaGetSymbolAddress((void**)&t1h,   g_t1_hi);
        cudaGetSymbolAddress((void**)&t1l,   g_t1_lo);
        cudaGetSymbolAddress((void**)&x,     g_x);
        cudaGetSymbolAddress((void**)&t2,    g_t2);
        cudaFuncSetAttribute((void*)(gemm_t)gemm_fp16<64, 64, 2, 4, 256, 3, 2, 64>,
                             cudaFuncAttributeMaxDynamicSharedMemorySize, SMEM_SMALL);
        cudaFuncSetAttribute((void*)(gemm_t)gemm_fp16<64, 64, 2, 4, 256, 3, 1, 64>,
                             cudaFuncAttributeMaxDynamicSharedMemorySize, SMEM_COMB);
        cudaFuncSetAttribute((void*)(gemm_t)gemm_fp16<128, 256, 4, 4, 512, 4, 1, 32>,
                             cudaFuncAttributeMaxDynamicSharedMemorySize, SMEM_UNE);
        cudaStreamCreateWithFlags(&s2, cudaStreamNonBlocking);
        cudaStreamCreateWithFlags(&s3, cudaStreamNonBlocking);
        cudaEventCreateWithFlags(&evStart, cudaEventDisableTiming);
        cudaEventCreateWithFlags(&evDone,  cudaEventDisableTiming);
        for (int i = 0; i < HH; i++) {
            cudaEventCreateWithFlags(&evH[i],  cudaEventDisableTiming);
            cudaEventCreateWithFlags(&evSA[i], cudaEventDisableTiming);
            cudaEventCreateWithFlags(&evCA[i], cudaEventDisableTiming);
        }
    }

    // fork side streams
    cudaEventRecord(evStart, 0);
    cudaStreamWaitEvent(s2, evStart, 0);
    cudaStreamWaitEvent(s3, evStart, 0);

    // s2: unembed weight conversion (only unembed consumes it)
    conv_w<<<2048, 256, 0, s2>>>(unemb_w, wh + OFF_UNE, 32768000 / 4);

    // s3: combined attention weights  W2 = wo @ wv, b2 = bo + wo @ bv
    conv_w<<<1024, 256, 0, s3>>>(sa_wo, wh + OFF_SAWO, 4194304 / 4);
    conv_w<<<1024, 256, 0, s3>>>(ca_wo, wh + OFF_CAWO, 4194304 / 4);
    for (int h = 0; h < HH; h++) {
        // sa
        transp_kernel<<<dim3(32, 32), dim3(32, 8), 0, s3>>>(sa_wv + (size_t)h * DD * DD, wvT);
        comb_bias_kernel<<<DD / 8, 256, 0, s3>>>(sa_wo + (size_t)h * DD * DD,
                                                 sa_bv + (size_t)h * DD,
                                                 sa_bo + (size_t)h * DD, b2 + (size_t)(2 * h) * DD);
        gemm_fp16<64, 64, 2, 4, 256, 3, 1, 64><<<dim3(DD / 64, DD / 64), 256, SMEM_COMB, s3>>>(
            wh + OFF_SAWO + (size_t)h * DD * DD, nullptr, wvT, zero,
            nullptr, 0, wcomb + (size_t)(2 * h) * DD * DD, nullptr, DD, DD, 0);
        cudaEventRecord(evSA[h], s3);
        // ca
        transp_kernel<<<dim3(32, 32), dim3(32, 8), 0, s3>>>(ca_wv + (size_t)h * DD * DD, wvT);
        comb_bias_kernel<<<DD / 8, 256, 0, s3>>>(ca_wo + (size_t)h * DD * DD,
                                                 ca_bv + (size_t)h * DD,
                                                 ca_bo + (size_t)h * DD, b2 + (size_t)(2 * h + 1) * DD);
        gemm_fp16<64, 64, 2, 4, 256, 3, 1, 64><<<dim3(DD / 64, DD / 64), 256, SMEM_COMB, s3>>>(
            wh + OFF_CAWO + (size_t)h * DD * DD, nullptr, wvT, zero,
            nullptr, 0, wcomb + (size_t)(2 * h + 1) * DD * DD, nullptr, DD, DD, 0);
        cudaEventRecord(evCA[h], s3);
    }

    // main stream: chain weight conversions
    conv_w<<<1024, 256>>>(proj_w, wh + OFF_PROJ, 8388608 / 4);
    conv_w<<<1024, 256>>>(ff_w1,  wh + OFF_FF1,  8388608 / 4);
    conv_w<<<1024, 256>>>(ff_w2,  wh + OFF_FF2,  8388608 / 4);

    init_h_kernel<<<MM, 256>>>(hidden, x);

    for (int h = 0; h < HH; h++) {
        __half *XH = xhB + (size_t)h * MM * DD;
        __half *XL = xlB + (size_t)h * MM * DD;

        prep_kernel<<<dim3(MM, 2), 256>>>(tok, emb, x, rms_w, xch, xcl, h);

        gemm_fp16<64, 64, 2, 4, 256, 3, 2, 64><<<dim3(MM / 64, DD / 64), 256, SMEM_SMALL>>>(
            xch, xcl, wh + OFF_PROJ + (size_t)h * 2097152,
            proj_b + (size_t)h * DD, x, DD, XH, XL, DD, 2 * DD, 0);

        // sa block (combined): t2 = x @ W2sa^T + b2sa
        cudaStreamWaitEvent(0, evSA[h], 0);
        gemm_fp16<64, 64, 2, 4, 256, 3, 2, 64><<<dim3(MM / 64, DD / 64), 256, SMEM_SMALL>>>(
            XH, XL, wcomb + (size_t)(2 * h) * DD * DD,
            b2 + (size_t)(2 * h) * DD, t2, DD, nullptr, nullptr, 0, DD, 0);
        resid_ln_kernel<<<MM, 256>>>(x, t2, ln1_w + (size_t)h * DD, ln1_b + (size_t)h * DD, XH, XL);

        // ca block (combined)
        cudaStreamWaitEvent(0, evCA[h], 0);
        gemm_fp16<64, 64, 2, 4, 256, 3, 2, 64><<<dim3(MM / 64, DD / 64), 256, SMEM_SMALL>>>(
            XH, XL, wcomb + (size_t)(2 * h + 1) * DD * DD,
            b2 + (size_t)(2 * h + 1) * DD, t2, DD, nullptr, nullptr, 0, DD, 0);
        resid_ln_kernel<<<MM, 256>>>(x, t2, ln2_w + (size_t)h * DD, ln2_b + (size_t)h * DD, XH, XL);

        // FFN
        gemm_fp16<64, 64, 2, 4, 256, 3, 2, 64><<<dim3(MM / 64, DFF / 64), 256, SMEM_SMALL>>>(
            XH, XL, wh + OFF_FF1 + (size_t)h * 2097152,
            ff_b1 + (size_t)h * DFF, nullptr, 0, t1h, t1l, DFF, DD, 1);
        gemm_fp16<64, 64, 2, 4, 256, 3, 2, 64><<<dim3(MM / 64, DD / 64), 256, SMEM_SMALL>>>(
            t1h, t1l, wh + OFF_FF2 + (size_t)h * 2097152,
            ff_b2 + (size_t)h * DD, t2, DD, nullptr, nullptr, 0, DFF, 0);
        resid_ln_kernel<<<MM, 256>>>(x, t2, ln3_w + (size_t)h * DD, ln3_b + (size_t)h * DD, XH, XL);

        // unembed on s2
        cudaEventRecord(evH[h], 0);
        cudaStreamWaitEvent(s2, evH[h], 0);
        gemm_fp16<128, 256, 4, 4, 512, 4, 1, 32><<<dim3(MM / 128, VV / 256), 512, SMEM_UNE, s2>>>(
            XH, nullptr, wh + OFF_UNE,
            unemb_b, out + (size_t)h * VV, (long long)HH * VV, nullptr, nullptr, 0, DD, 0);
    }

    // join side streams
    cudaEventRecord(evDone, s2);
    cudaStreamWaitEvent(0, evDone, 0);
    cudaEventRecord(evStart, s3);   // reuse event object for join (distinct capture node)
    cudaStreamWaitEvent(0, evStart, 0);
}

// round 17
// speedup vs baseline: 1.3603x; 1.1019x over previous
#include <cuda_runtime.h>
#include <cuda_fp16.h>
#include <cstdint>

// Problem constants
#define BB   2
#define TT   260
#define HH   4
#define DD   1024
#define VV   32000
#define DFF  2048
#define MM   512

// ---------------------------------------------------------------------------
// Persistent scratch (__device__ globals; no allocations allowed)
// ---------------------------------------------------------------------------
#define OFF_PROJ 0
#define OFF_SAWO 8388608
#define OFF_CAWO 12582912
#define OFF_FF1  16777216
#define OFF_FF2  25165824
#define OFF_UNE  33554432
#define W_TOTAL  66322432

__device__ __half g_wh[W_TOTAL];                 // fp16 weights (conv'd per launch)
__device__ __half g_wcomb[8 * DD * DD];          // combined sa/ca weights
__device__ float  g_b2[8 * DD];                  // combined biases
__device__ __half g_wvT[DD * DD];                // transpose scratch (s3-serial)
__device__ float  g_zero[DFF];                   // zero bias

__device__ float g_x  [MM * DD];
__device__ float g_t2 [MM * DD];
__device__ __half g_xc[MM * 2 * DD];             // fp16 activations (single)
__device__ __half g_xh[HH][MM * DD];             // per-head final activations
__device__ __half g_t1[MM * DFF];

// ---------------------------------------------------------------------------
// helpers
// ---------------------------------------------------------------------------
__device__ __forceinline__ float block_sum(float v) {
    __shared__ float sh[32];
    const int lane = threadIdx.x & 31;
    const int wid  = threadIdx.x >> 5;
    #pragma unroll
    for (int o = 16; o; o >>= 1) v += __shfl_xor_sync(0xffffffffu, v, o);
    if (lane == 0) sh[wid] = v;
    __syncthreads();
    if (wid == 0) {
        v = (lane < 8) ? sh[lane] : 0.0f;
        #pragma unroll
        for (int o = 4; o; o >>= 1) v += __shfl_xor_sync(0xffffffffu, v, o);
        if (lane == 0) sh[0] = v;
    }
    __syncthreads();
    v = sh[0];
    __syncthreads();
    return v;
}

__device__ __forceinline__ uint32_t s2u(const void* p) {
    uint32_t a;
    asm("{ .reg .u64 t; cvta.to.shared.u64 t, %1; cvt.u32.u64 %0, t; }" : "=r"(a) : "l"(p));
    return a;
}
__device__ __forceinline__ void ldsm4(uint32_t* r, uint32_t addr) {
    asm volatile("ldmatrix.sync.aligned.m8n8.x4.shared.b16 {%0,%1,%2,%3}, [%4];"
                 : "=r"(r[0]), "=r"(r[1]), "=r"(r[2]), "=r"(r[3]) : "r"(addr));
}
__device__ __forceinline__ void mma_f16(float* c, const uint32_t* a, const uint32_t* b) {
    asm volatile(
        "mma.sync.aligned.m16n8k16.row.col.f32.f16.f16.f32 "
        "{%0,%1,%2,%3}, {%4,%5,%6,%7}, {%8,%9}, {%0,%1,%2,%3};"
        : "+f"(c[0]), "+f"(c[1]), "+f"(c[2]), "+f"(c[3])
        : "r"(a[0]), "r"(a[1]), "r"(a[2]), "r"(a[3]), "r"(b[0]), "r"(b[1]));
}
__device__ __forceinline__ uint32_t pack_h2(__half a, __half b) {
    __half2 p = __halves2half2(a, b);
    return *reinterpret_cast<uint32_t*>(&p);
}

// ---------------------------------------------------------------------------
// weight conversion: fp32 -> single fp16
// ---------------------------------------------------------------------------
__global__ void conv_w(const float* __restrict__ src, __half* __restrict__ dst, int n4) {
    int i = blockIdx.x * blockDim.x + threadIdx.x;
    const int stride = gridDim.x * blockDim.x;
    for (; i < n4; i += stride) {
        float4 v = ((const float4*)src)[i];
        uint32_t p0 = pack_h2(__float2half_rn(v.x), __float2half_rn(v.y));
        uint32_t p1 = pack_h2(__float2half_rn(v.z), __float2half_rn(v.w));
        ((uint2*)dst)[i] = make_uint2(p0, p1);
    }
}

// transpose + convert: dst[k][n] = fp16(src[n][k]), DxD
__global__ void transp_kernel(const float* __restrict__ src, __half* __restrict__ dst) {
    __shared__ float tile[32][33];
    const int n0 = blockIdx.x * 32, k0 = blockIdx.y * 32;
    for (int i = threadIdx.y; i < 32; i += 8)
        tile[i][threadIdx.x] = src[(size_t)(n0 + i) * DD + k0 + threadIdx.x];
    __syncthreads();
    for (int i = threadIdx.y; i < 32; i += 8)
        dst[(size_t)(k0 + i) * DD + n0 + threadIdx.x] = __float2half_rn(tile[threadIdx.x][i]);
}

// b2[p] = bo[p] + dot(wo[p,:], bv)
__global__ void comb_bias_kernel(const float* __restrict__ wo, const float* __restrict__ bv,
                                 const float* __restrict__ bo, float* __restrict__ b2) {
    const int w = threadIdx.x >> 5, lane = threadIdx.x & 31;
    const int p = blockIdx.x * 8 + w;
    const float* row = wo + (size_t)p * DD;
    float s = 0.0f;
    for (int n = lane; n < DD; n += 32) s += row[n] * bv[n];
    #pragma unroll
    for (int o = 16; o; o >>= 1) s += __shfl_xor_sync(0xffffffffu, s, o);
    if (lane == 0) b2[p] = s + bo[p];
}

__global__ void init_h_kernel(const float* __restrict__ hidden, float* __restrict__ hbuf) {
    const int m = blockIdx.x;
    const int b = m >> 8, j = m & 255;
    const float* src = hidden + ((size_t)b * TT + j) * DD;
    float* dst = hbuf + (size_t)m * DD;
    #pragma unroll
    for (int i = 0; i < 4; i++) dst[threadIdx.x + i * 256] = src[threadIdx.x + i * 256];
}

__global__ void prep_kernel(const int* __restrict__ tok,
                            const float* __restrict__ emb,
                            const float* __restrict__ hprev,
                            const float* __restrict__ rms_w,
                            __half* __restrict__ xc, int h) {
    const int m = blockIdx.x;
    const int half = blockIdx.y;
    const int tid = threadIdx.x;
    const int b = m >> 8, j = m & 255;
    const float* src;
    if (half == 0) {
        const int t = tok[b * TT + 1 + h + j];
        src = emb + (size_t)t * DD;
    } else {
        src = hprev + (size_t)m * DD;
    }
    float v[4];
    float ss = 0.0f;
    #pragma unroll
    for (int i = 0; i < 4; i++) { v[i] = src[tid + i * 256]; ss += v[i] * v[i]; }
    ss = block_sum(ss);
    const float s = rsqrtf(ss * (1.0f / DD) + 1e-6f);
    const size_t base = (size_t)m * (2 * DD) + half * DD;
    #pragma unroll
    for (int i = 0; i < 4; i++) {
        const int d = tid + i * 256;
        xc[base + d] = __float2half_rn(v[i] * s * rms_w[d]);
    }
}

__global__ void resid_ln_kernel(float* __restrict__ x, const float* __restrict__ u,
                                const float* __restrict__ w, const float* __restrict__ bb,
                                __half* __restrict__ oh) {
    const int m = blockIdx.x;
    const int tid = threadIdx.x;
    float* xr = x + (size_t)m * DD;
    const float* ur = u + (size_t)m * DD;
    float v[4];
    float s = 0.0f;
    #pragma unroll
    for (int i = 0; i < 4; i++) {
        v[i] = xr[tid + i * 256] + ur[tid + i * 256];
        s += v[i];
    }
    s = block_sum(s);
    const float mu = s * (1.0f / DD);
    float s2 = 0.0f;
    #pragma unroll
    for (int i = 0; i < 4; i++) { const float d = v[i] - mu; s2 += d * d; }
    s2 = block_sum(s2);
    const float rs = rsqrtf(s2 * (1.0f / DD) + 1e-5f);
    #pragma unroll
    for (int i = 0; i < 4; i++) {
        const int d = tid + i * 256;
        const float f = (v[i] - mu) * rs * w[d] + bb[d];
        xr[d] = f;
        oh[(size_t)m * DD + d] = __float2half_rn(f);
    }
}

// ---------------------------------------------------------------------------
// fp16 GEMM (single-product): C[m,n] = sum_k A[m,k]*B[n,k] + bias[n]
// Outputs: optional fp32 C, optional fp16 O.
// ---------------------------------------------------------------------------
template<int BM, int BN, int WGM, int WGN, int NTH, int S, int BK>
__global__ void __launch_bounds__(NTH) gemm_fp16(
    const __half* __restrict__ Ah,
    const __half* __restrict__ Bh,
    const float* __restrict__ bias,
    float* __restrict__ C, long long ldc,
    __half* __restrict__ Oh, int ldo,
    int K, int relu)
{
    constexpr int WM  = BM / WGM;
    constexpr int WN  = BN / WGN;
    constexpr int MI  = WM / 16;
    constexpr int NI  = WN / 8;
    constexpr int LS  = BK + 8;
    constexpr int CPR = BK / 8;
    constexpr int AT  = BM * LS * 2;
    constexpr int BT  = BN * LS * 2;
    constexpr int STAGE = AT + BT;
    constexpr int NKS = BK / 16;

    extern __shared__ char smem[];
    const uint32_t sb = s2u(smem);

    const int tid  = threadIdx.x;
    const int wid  = tid >> 5;
    const int lane = tid & 31;
    const int wm   = wid / WGN;
    const int wn   = wid % WGN;
    const int m0   = blockIdx.x * BM;
    const int n0   = blockIdx.y * BN;
    const int nCh  = K / BK;

    float acc[MI][NI][4];
    #pragma unroll
    for (int i = 0; i < MI; i++)
        #pragma unroll
        for (int j = 0; j < NI; j++)
            #pragma unroll
            for (int q = 0; q < 4; q++) acc[i][j][q] = 0.0f;

    auto issue = [&](int c) {
        if (c < nCh) {
            const int k0 = c * BK;
            const uint32_t st = sb + (uint32_t)(c % S) * STAGE;
            #pragma unroll
            for (int q = tid; q < BM * CPR; q += NTH) {
                const int row = q / CPR, col = (q % CPR) * 8;
                const size_t off = (size_t)(m0 + row) * K + k0 + col;
                const uint32_t d = st + (uint32_t)(row * LS + col) * 2u;
                asm volatile("cp.async.cg.shared.global [%0], [%1], 16;" :: "r"(d), "l"(Ah + off));
            }
            #pragma unroll
            for (int q = tid; q < BN * CPR; q += NTH) {
                const int row = q / CPR, col = (q % CPR) * 8;
                const size_t off = (size_t)(n0 + row) * K + k0 + col;
                const uint32_t d = st + AT + (uint32_t)(row * LS + col) * 2u;
                asm volatile("cp.async.cg.shared.global [%0], [%1], 16;" :: "r"(d), "l"(Bh + off));
            }
        }
        asm volatile("cp.async.commit_group;" ::: "memory");
    };

    #pragma unroll
    for (int p = 0; p < S - 1; p++) issue(p);

    for (int c = 0; c < nCh; c++) {
        asm volatile("cp.async.wait_group %0;" :: "n"(S - 2) : "memory");
        __syncthreads();
        issue(c + S - 1);

        const uint32_t st  = sb + (uint32_t)(c % S) * STAGE;
        const uint32_t sAh = st;
        const uint32_t sBh = st + AT;
        #pragma unroll
        for (int ks = 0; ks < NKS; ks++) {
            uint32_t ah[MI][4];
            #pragma unroll
            for (int mi = 0; mi < MI; mi++) {
                const int row = wm * WM + mi * 16 + (lane & 15);
                const int col = ks * 16 + (lane >> 4) * 8;
                ldsm4(ah[mi], sAh + (uint32_t)(row * LS + col) * 2u);
            }
            uint32_t bh[NI][2];
            #pragma unroll
            for (int ni = 0; ni < NI; ni += 2) {
                const int g = lane >> 3;
                const int row = wn * WN + ni * 8 + ((g >> 1) << 3) + (lane & 7);
                const int col = ks * 16 + ((g & 1) << 3);
                ldsm4(&bh[ni][0], sBh + (uint32_t)(row * LS + col) * 2u);
            }
            #pragma unroll
            for (int mi = 0; mi < MI; mi++)
                #pragma unroll
                for (int ni = 0; ni < NI; ni++)
                    mma_f16(acc[mi][ni], ah[mi], bh[ni]);
        }
    }

    #pragma unroll
    for (int mi = 0; mi < MI; mi++) {
        #pragma unroll
        for (int ni = 0; ni < NI; ni++) {
            const int r0 = m0 + wm * WM + mi * 16 + (lane >> 2);
            const int cc = n0 + wn * WN + ni * 8 + ((lane & 3) << 1);
            const float b0 = bias[cc], b1 = bias[cc + 1];
            float v0 = acc[mi][ni][0] + b0;
            float v1 = acc[mi][ni][1] + b1;
            float v2 = acc[mi][ni][2] + b0;
            float v3 = acc[mi][ni][3] + b1;
            if (relu) {
                v0 = fmaxf(v0, 0.0f); v1 = fmaxf(v1, 0.0f);
                v2 = fmaxf(v2, 0.0f); v3 = fmaxf(v3, 0.0f);
            }
            if (C) {
                *(float2*)(C + (size_t)r0 * (size_t)ldc + cc)       = make_float2(v0, v1);
                *(float2*)(C + (size_t)(r0 + 8) * (size_t)ldc + cc) = make_float2(v2, v3);
            }
            if (Oh) {
                *(uint32_t*)(Oh + (size_t)r0 * ldo + cc) =
                    pack_h2(__float2half_rn(v0), __float2half_rn(v1));
                *(uint32_t*)(Oh + (size_t)(r0 + 8) * ldo + cc) =
                    pack_h2(__float2half_rn(v2), __float2half_rn(v3));
            }
        }
    }
}

// chain & combine: 64x64, BK=64, S=3 -> 3*(64+64)*72*2 = 55296 B
#define SMEM_SMALL (3 * ((64 + 64) * 72 * 2))
// unembed: 128x256, BK=32, S=4 -> 4*(128+256)*40*2 = 122880 B
#define SMEM_UNE   (4 * ((128 + 256) * 40 * 2))

typedef void (*gemm_t)(const __half*, const __half*, const float*,
                       float*, long long, __half*, int, int, int);

// ---------------------------------------------------------------------------
// Host orchestration
// ---------------------------------------------------------------------------
extern "C" void kernel_launch(void* const* d_in, const int* in_sizes, int n_in,
                              void* d_out, int out_size) {
    const int*   tok     = (const int*)  d_in[0];
    const float* hidden  = (const float*)d_in[1];
    const float* emb     = (const float*)d_in[2];
    const float* rms_w   = (const float*)d_in[3];
    const float* proj_w  = (const float*)d_in[4];
    const float* proj_b  = (const float*)d_in[5];
    const float* sa_wv   = (const float*)d_in[6];
    const float* sa_bv   = (const float*)d_in[7];
    const float* sa_wo   = (const float*)d_in[8];
    const float* sa_bo   = (const float*)d_in[9];
    const float* ca_wv   = (const float*)d_in[10];
    const float* ca_bv   = (const float*)d_in[11];
    const float* ca_wo   = (const float*)d_in[12];
    const float* ca_bo   = (const float*)d_in[13];
    const float* ln1_w   = (const float*)d_in[14];
    const float* ln1_b   = (const float*)d_in[15];
    const float* ln2_w   = (const float*)d_in[16];
    const float* ln2_b   = (const float*)d_in[17];
    const float* ln3_w   = (const float*)d_in[18];
    const float* ln3_b   = (const float*)d_in[19];
    const float* ff_w1   = (const float*)d_in[20];
    const float* ff_b1   = (const float*)d_in[21];
    const float* ff_w2   = (const float*)d_in[22];
    const float* ff_b2   = (const float*)d_in[23];
    const float* unemb_w = (const float*)d_in[24];
    const float* unemb_b = (const float*)d_in[25];
    float* out = (float*)d_out;

    static __half *wh = nullptr, *wcomb = nullptr, *wvT = nullptr;
    static float  *b2 = nullptr, *zero = nullptr;
    static __half *xc = nullptr, *xhB = nullptr, *t1 = nullptr;
    static float *x = nullptr, *t2 = nullptr;
    static cudaStream_t s2 = nullptr, s3 = nullptr;
    static cudaEvent_t evStart = nullptr, evDone = nullptr, evJoin3 = nullptr;
    static cudaEvent_t evH[HH] = {}, evSA[HH] = {}, evCA[HH] = {};
    if (!wh) {
        cudaGetSymbolAddress((void**)&wh,    g_wh);
        cudaGetSymbolAddress((void**)&wcomb, g_wcomb);
        cudaGetSymbolAddress((void**)&wvT,   g_wvT);
        cudaGetSymbolAddress((void**)&b2,    g_b2);
        cudaGetSymbolAddress((void**)&zero,  g_zero);
        cudaGetSymbolAddress((void**)&xc,    g_xc);
        cudaGetSymbolAddress((void**)&xhB,   g_xh);
        cudaGetSymbolAddress((void**)&t1,    g_t1);
        cudaGetSymbolAddress((void**)&x,     g_x);
        cudaGetSymbolAddress((void**)&t2,    g_t2);
        cudaFuncSetAttribute((void*)(gemm_t)gemm_fp16<64, 64, 2, 4, 256, 3, 64>,
                             cudaFuncAttributeMaxDynamicSharedMemorySize, SMEM_SMALL);
        cudaFuncSetAttribute((void*)(gemm_t)gemm_fp16<128, 256, 4, 4, 512, 4, 32>,
                             cudaFuncAttributeMaxDynamicSharedMemorySize, SMEM_UNE);
        cudaStreamCreateWithFlags(&s2, cudaStreamNonBlocking);
        cudaStreamCreateWithFlags(&s3, cudaStreamNonBlocking);
        cudaEventCreateWithFlags(&evStart, cudaEventDisableTiming);
        cudaEventCreateWithFlags(&evDone,  cudaEventDisableTiming);
        cudaEventCreateWithFlags(&evJoin3, cudaEventDisableTiming);
        for (int i = 0; i < HH; i++) {
            cudaEventCreateWithFlags(&evH[i],  cudaEventDisableTiming);
            cudaEventCreateWithFlags(&evSA[i], cudaEventDisableTiming);
            cudaEventCreateWithFlags(&evCA[i], cudaEventDisableTiming);
        }
    }

    // fork side streams
    cudaEventRecord(evStart, 0);
    cudaStreamWaitEvent(s2, evStart, 0);
    cudaStreamWaitEvent(s3, evStart, 0);

    // s2: unembed weight conversion
    conv_w<<<2048, 256, 0, s2>>>(unemb_w, wh + OFF_UNE, 32768000 / 4);

    // s3: combined attention weights  W2 = wo @ wv, b2 = bo + wo @ bv
    conv_w<<<1024, 256, 0, s3>>>(sa_wo, wh + OFF_SAWO, 4194304 / 4);
    conv_w<<<1024, 256, 0, s3>>>(ca_wo, wh + OFF_CAWO, 4194304 / 4);
    for (int h = 0; h < HH; h++) {
        transp_kernel<<<dim3(32, 32), dim3(32, 8), 0, s3>>>(sa_wv + (size_t)h * DD * DD, wvT);
        comb_bias_kernel<<<DD / 8, 256, 0, s3>>>(sa_wo + (size_t)h * DD * DD,
                                                 sa_bv + (size_t)h * DD,
                                                 sa_bo + (size_t)h * DD, b2 + (size_t)(2 * h) * DD);
        gemm_fp16<64, 64, 2, 4, 256, 3, 64><<<dim3(DD / 64, DD / 64), 256, SMEM_SMALL, s3>>>(
            wh + OFF_SAWO + (size_t)h * DD * DD, wvT, zero,
            nullptr, 0, wcomb + (size_t)(2 * h) * DD * DD, DD, DD, 0);
        cudaEventRecord(evSA[h], s3);
        transp_kernel<<<dim3(32, 32), dim3(32, 8), 0, s3>>>(ca_wv + (size_t)h * DD * DD, wvT);
        comb_bias_kernel<<<DD / 8, 256, 0, s3>>>(ca_wo + (size_t)h * DD * DD,
                                                 ca_bv + (size_t)h * DD,
                                                 ca_bo + (size_t)h * DD, b2 + (size_t)(2 * h + 1) * DD);
        gemm_fp16<64, 64, 2, 4, 256, 3, 64><<<dim3(DD / 64, DD / 64), 256, SMEM_SMALL, s3>>>(
            wh + OFF_CAWO + (size_t)h * DD * DD, wvT, zero,
            nullptr, 0, wcomb + (size_t)(2 * h + 1) * DD * DD, DD, DD, 0);
        cudaEventRecord(evCA[h], s3);
    }

    // main stream: chain weight conversions
    conv_w<<<1024, 256>>>(proj_w, wh + OFF_PROJ, 8388608 / 4);
    conv_w<<<1024, 256>>>(ff_w1,  wh + OFF_FF1,  8388608 / 4);
    conv_w<<<1024, 256>>>(ff_w2,  wh + OFF_FF2,  8388608 / 4);

    init_h_kernel<<<MM, 256>>>(hidden, x);

    for (int h = 0; h < HH; h++) {
        __half *XH = xhB + (size_t)h * MM * DD;

        prep_kernel<<<dim3(MM, 2), 256>>>(tok, emb, x, rms_w, xc, h);

        gemm_fp16<64, 64, 2, 4, 256, 3, 64><<<dim3(MM / 64, DD / 64), 256, SMEM_SMALL>>>(
            xc, wh + OFF_PROJ + (size_t)h * 2097152,
            proj_b + (size_t)h * DD, x, DD, XH, DD, 2 * DD, 0);

        // sa block (combined): t2 = x @ W2sa^T + b2sa
        cudaStreamWaitEvent(0, evSA[h], 0);
        gemm_fp16<64, 64, 2, 4, 256, 3, 64><<<dim3(MM / 64, DD / 64), 256, SMEM_SMALL>>>(
            XH, wcomb + (size_t)(2 * h) * DD * DD,
            b2 + (size_t)(2 * h) * DD, t2, DD, nullptr, 0, DD, 0);
        resid_ln_kernel<<<MM, 256>>>(x, t2, ln1_w + (size_t)h * DD, ln1_b + (size_t)h * DD, XH);

        // ca block (combined)
        cudaStreamWaitEvent(0, evCA[h], 0);
        gemm_fp16<64, 64, 2, 4, 256, 3, 64><<<dim3(MM / 64, DD / 64), 256, SMEM_SMALL>>>(
            XH, wcomb + (size_t)(2 * h + 1) * DD * DD,
            b2 + (size_t)(2 * h + 1) * DD, t2, DD, nullptr, 0, DD, 0);
        resid_ln_kernel<<<MM, 256>>>(x, t2, ln2_w + (size_t)h * DD, ln2_b + (size_t)h * DD, XH);

        // FFN
        gemm_fp16<64, 64, 2, 4, 256, 3, 64><<<dim3(MM / 64, DFF / 64), 256, SMEM_SMALL>>>(
            XH, wh + OFF_FF1 + (size_t)h * 2097152,
            ff_b1 + (size_t)h * DFF, nullptr, 0, t1, DFF, DD, 1);
        gemm_fp16<64, 64, 2, 4, 256, 3, 64><<<dim3(MM / 64, DD / 64), 256, SMEM_SMALL>>>(
            t1, wh + OFF_FF2 + (size_t)h * 2097152,
            ff_b2 + (size_t)h * DD, t2, DD, nullptr, 0, DFF, 0);
        resid_ln_kernel<<<MM, 256>>>(x, t2, ln3_w + (size_t)h * DD, ln3_b + (size_t)h * DD, XH);

        // unembed on s2
        cudaEventRecord(evH[h], 0);
        cudaStreamWaitEvent(s2, evH[h], 0);
        gemm_fp16<128, 256, 4, 4, 512, 4, 32><<<dim3(MM / 128, VV / 256), 512, SMEM_UNE, s2>>>(
            XH, wh + OFF_UNE,
            unemb_b, out + (size_t)h * VV, (long long)HH * VV, nullptr, 0, DD, 0);
    }

    // join side streams
    cudaEventRecord(evDone, s2);
    cudaStreamWaitEvent(0, evDone, 0);
    cudaEventRecord(evJoin3, s3);
    cudaStreamWaitEvent(0, evJoin3, 0);
}